// round 9
// baseline (speedup 1.0000x reference)
#include <cuda_runtime.h>

// Problem constants
#define B_      256
#define L_      2048
#define V_      8
#define NS_     5        // shapelets
#define BAG_    409
#define BAGP_   416      // padded (zero-filled) shapelet length in smem
#define SHIFT_  204
#define NB_     9        // windows
#define FEAT_   80       // 2*NS*V
#define NCLASS_ 10
#define BN_EPS_ 1e-5f
#define RSTRIDE_ 57      // padded reduction row stride (conflict-free)

// Scratch
__device__ float g_feat[B_ * FEAT_];
__device__ float g_scale[FEAT_];
__device__ float g_shift[FEAT_];

#define K1_WARPS_   4
#define K1_THREADS_ (K1_WARPS_ * 32)
#define RED_FLOATS_ (K1_WARPS_ * 32 * RSTRIDE_)   // per-block reduction scratch
#define K1_DSMEM_   (RED_FLOATS_ * sizeof(float))

// ---------------------------------------------------------------------------
// Kernel 1: block = (4 batches, 1 v), one warp per (b,v). Grid 512.
// t vectorized: 3 float4 chunks (t<384) + scalar tail (25).
// Inner loop holds all 5 shapelet float4s and streams ONE window's xv at a
// time (4 live regs, 24 FMAs per load) -> live set ~90 regs, cap 102,
// 20 warps/SM instead of the 128-reg/16-warp cap.
// ---------------------------------------------------------------------------
__global__ __launch_bounds__(K1_THREADS_, 5)
void shapelet_feat_kernel(const float* __restrict__ x,
                          const float* __restrict__ shp,
                          float* __restrict__ feat)
{
    extern __shared__ float red[];          // [4][32][RSTRIDE_]
    __shared__ float s_shp[NS_][BAGP_];
    __shared__ float s_ss2[NS_];

    const int tid  = threadIdx.x;
    const int warp = tid >> 5;
    const int lane = tid & 31;
    const int v  = blockIdx.x & 7;
    const int b  = (blockIdx.x >> 3) * K1_WARPS_ + warp;

    // Stage shapelets (zero-pad 409..415)
    for (int i = tid; i < NS_ * BAGP_; i += K1_THREADS_) {
        const int s = i / BAGP_;
        const int t = i - s * BAGP_;
        s_shp[s][t] = (t < BAG_) ? shp[s * (V_ * BAG_) + v * BAG_ + t] : 0.f;
    }
    __syncthreads();

    // ss2[s]: warps take s = warp, warp+4
    for (int s = warp; s < NS_; s += K1_WARPS_) {
        float q = 0.f;
        for (int t = lane; t < BAG_; t += 32) {
            const float sv = s_shp[s][t];
            q = fmaf(sv, sv, q);
        }
#pragma unroll
        for (int o = 16; o > 0; o >>= 1) q += __shfl_xor_sync(0xffffffffu, q, o);
        if (lane == 0) s_ss2[s] = q;
    }

    // ---- main accumulation ----
    const float* __restrict__ xr = x + (size_t)b * (V_ * L_) + (size_t)v * L_;
    const float* __restrict__ xr4 = xr + 4 * lane;

    float c[NS_][NB_];
    float sx2[NB_];
#pragma unroll
    for (int s = 0; s < NS_; s++)
#pragma unroll
        for (int nb = 0; nb < NB_; nb++) c[s][nb] = 0.f;
#pragma unroll
    for (int nb = 0; nb < NB_; nb++) sx2[nb] = 0.f;

#pragma unroll
    for (int k = 0; k < 3; k++) {
        const int t0 = 128 * k + 4 * lane;

        // hold all 5 shapelet vectors for this chunk (reused by 9 windows)
        float4 sw[NS_];
#pragma unroll
        for (int s = 0; s < NS_; s++)
            sw[s] = *(const float4*)(&s_shp[s][t0]);

        // stream windows one at a time: 1 LDG.128 -> 24 FMAs
#pragma unroll
        for (int nb = 0; nb < NB_; nb++) {
            const float4 xv = *(const float4*)(xr4 + nb * SHIFT_ + 128 * k);
            sx2[nb] = fmaf(xv.x, xv.x, sx2[nb]);
            sx2[nb] = fmaf(xv.y, xv.y, sx2[nb]);
            sx2[nb] = fmaf(xv.z, xv.z, sx2[nb]);
            sx2[nb] = fmaf(xv.w, xv.w, sx2[nb]);
#pragma unroll
            for (int s = 0; s < NS_; s++) {
                c[s][nb] = fmaf(xv.x, sw[s].x, c[s][nb]);
                c[s][nb] = fmaf(xv.y, sw[s].y, c[s][nb]);
                c[s][nb] = fmaf(xv.z, sw[s].z, c[s][nb]);
                c[s][nb] = fmaf(xv.w, sw[s].w, c[s][nb]);
            }
        }
    }

    // scalar tail: t = 384 + lane, valid for lane < 25
    {
        const int t = 384 + lane;
        const bool ok = (lane < 25);
        float xs[NB_];
#pragma unroll
        for (int nb = 0; nb < NB_; nb++)
            xs[nb] = ok ? xr[nb * SHIFT_ + t] : 0.f;
#pragma unroll
        for (int nb = 0; nb < NB_; nb++)
            sx2[nb] = fmaf(xs[nb], xs[nb], sx2[nb]);
#pragma unroll
        for (int s = 0; s < NS_; s++) {
            const float sv = s_shp[s][t];   // zero-padded, xs masked
#pragma unroll
            for (int nb = 0; nb < NB_; nb++)
                c[s][nb] = fmaf(xs[nb], sv, c[s][nb]);
        }
    }

    // ---- smem transpose reduction ----
    float* base = red + warp * (32 * RSTRIDE_);
    {
        float* my = base + lane * RSTRIDE_;
#pragma unroll
        for (int nb = 0; nb < NB_; nb++) my[nb] = sx2[nb];
#pragma unroll
        for (int s = 0; s < NS_; s++)
#pragma unroll
            for (int nb = 0; nb < NB_; nb++) my[NB_ + s * NB_ + nb] = c[s][nb];
    }
    __syncwarp();

    float tot0, tot1;
    if (lane < 27) {
        float a0 = 0.f, a1 = 0.f, b0 = 0.f, b1 = 0.f;
#pragma unroll
        for (int l = 0; l < 32; l += 2) {
            a0 += base[l * RSTRIDE_ + lane];
            a1 += base[(l + 1) * RSTRIDE_ + lane];
            b0 += base[l * RSTRIDE_ + lane + 27];
            b1 += base[(l + 1) * RSTRIDE_ + lane + 27];
        }
        tot0 = a0 + a1;
        tot1 = b0 + b1;
    }
    __syncwarp();
    if (lane < 27) {
        base[lane]      = tot0;
        base[lane + 27] = tot1;
    }
    __syncthreads();                         // also publishes s_ss2 to all warps

    // ---- epilogue: lanes 0..4 handle shapelet s = lane ----
    if (lane < NS_) {
        const int s = lane;
        const float ss2v = s_ss2[s];
        float dmin = 3.402823466e+38f;
        float dsum = 0.f;
#pragma unroll
        for (int nb = 0; nb < NB_; nb++) {
            const float sx2t = base[nb];
            const float ct   = base[NB_ + s * NB_ + nb];
            const float d2 = sx2t + ss2v - 2.f * ct;
            const float d  = sqrtf(fmaxf(d2, 0.f));
            dmin = fminf(dmin, d);
            dsum += d;
        }
        float* fout = feat + (size_t)b * FEAT_;
        fout[s * V_ + v]            = dmin;
        fout[NS_ * V_ + s * V_ + v] = dsum * (1.f / 9.f);
    }
}

// ---------------------------------------------------------------------------
// Kernel 2a: BN batch stats (two-pass). One block per feature, one thread per
// batch row. Writes scale[f] = gamma*rstd, shift[f] = beta - mu*scale.
// ---------------------------------------------------------------------------
__global__ __launch_bounds__(256, 8)
void bn_stats_kernel(const float* __restrict__ feat,
                     const float* __restrict__ gamma,
                     const float* __restrict__ beta,
                     float* __restrict__ scale,
                     float* __restrict__ shift)
{
    const int f = blockIdx.x;
    const int tid = threadIdx.x;
    __shared__ float ws[8];
    __shared__ float wq[8];

    const float v = feat[tid * FEAT_ + f];

    float s = v;
#pragma unroll
    for (int o = 16; o > 0; o >>= 1) s += __shfl_xor_sync(0xffffffffu, s, o);
    if ((tid & 31) == 0) ws[tid >> 5] = s;
    __syncthreads();

    const float mu = (ws[0] + ws[1] + ws[2] + ws[3] +
                      ws[4] + ws[5] + ws[6] + ws[7]) * (1.f / 256.f);

    const float d = v - mu;
    float q = d * d;
#pragma unroll
    for (int o = 16; o > 0; o >>= 1) q += __shfl_xor_sync(0xffffffffu, q, o);
    if ((tid & 31) == 0) wq[tid >> 5] = q;
    __syncthreads();

    if (tid == 0) {
        const float var = (wq[0] + wq[1] + wq[2] + wq[3] +
                           wq[4] + wq[5] + wq[6] + wq[7]) * (1.f / 256.f);
        const float rstd = rsqrtf(var + BN_EPS_);
        const float sc = gamma[f] * rstd;
        scale[f] = sc;
        shift[f] = beta[f] - mu * sc;
    }
}

// ---------------------------------------------------------------------------
// Kernel 2b: FC with BN folded. One block per class, one thread per batch row.
// ---------------------------------------------------------------------------
__global__ __launch_bounds__(256, 8)
void fc_kernel(const float* __restrict__ feat,
               const float* __restrict__ scale,
               const float* __restrict__ shift,
               const float* __restrict__ w,
               const float* __restrict__ fb,
               float* __restrict__ out)
{
    const int c = blockIdx.x;
    const int b = threadIdx.x;
    __shared__ float wp[FEAT_];
    __shared__ float cbias;

    if (b < FEAT_)
        wp[b] = w[c * FEAT_ + b] * scale[b];

    if (b >= 128 && b < 160) {
        // warp 4 computes the folded bias: fb[c] + sum_f shift[f]*w[c,f]
        const int lane = b - 128;
        float a = 0.f;
        for (int f = lane; f < FEAT_; f += 32)
            a = fmaf(shift[f], w[c * FEAT_ + f], a);
#pragma unroll
        for (int o = 16; o > 0; o >>= 1) a += __shfl_xor_sync(0xffffffffu, a, o);
        if (lane == 0) cbias = a + fb[c];
    }
    __syncthreads();

    const float4* __restrict__ fr = (const float4*)(feat + b * FEAT_);
    float acc = cbias;
#pragma unroll
    for (int i = 0; i < FEAT_ / 4; i++) {
        float4 xv = fr[i];
        acc = fmaf(xv.x, wp[4 * i + 0], acc);
        acc = fmaf(xv.y, wp[4 * i + 1], acc);
        acc = fmaf(xv.z, wp[4 * i + 2], acc);
        acc = fmaf(xv.w, wp[4 * i + 3], acc);
    }
    out[b * NCLASS_ + c] = acc;
}

// ---------------------------------------------------------------------------
extern "C" void kernel_launch(void* const* d_in, const int* in_sizes, int n_in,
                              void* d_out, int out_size)
{
    const float* x     = (const float*)d_in[0];  // [256, 2048, 8]
    const float* shp   = (const float*)d_in[1];  // [1, 5, 8, 409, 1]
    const float* gamma = (const float*)d_in[2];  // [80]
    const float* beta  = (const float*)d_in[3];  // [80]
    const float* fcw   = (const float*)d_in[4];  // [10, 80]
    const float* fcb   = (const float*)d_in[5];  // [10]
    float* out = (float*)d_out;                  // [256, 10]

    float *feat = nullptr, *scale = nullptr, *shift = nullptr;
    cudaGetSymbolAddress((void**)&feat,  g_feat);
    cudaGetSymbolAddress((void**)&scale, g_scale);
    cudaGetSymbolAddress((void**)&shift, g_shift);

    shapelet_feat_kernel<<<512, K1_THREADS_, K1_DSMEM_>>>(x, shp, feat);
    bn_stats_kernel<<<FEAT_, 256>>>(feat, gamma, beta, scale, shift);
    fc_kernel<<<NCLASS_, 256>>>(feat, scale, shift, fcw, fcb, out);
}

// round 10
// speedup vs baseline: 1.0911x; 1.0911x over previous
#include <cuda_runtime.h>

// Problem constants
#define B_      256
#define L_      2048
#define V_      8
#define NS_     5        // shapelets
#define BAG_    409
#define BAGP_   416      // padded (zero-filled) shapelet length in smem
#define SHIFT_  204
#define NB_     9        // windows
#define FEAT_   80       // 2*NS*V
#define NCLASS_ 10
#define BN_EPS_ 1e-5f
#define RSTRIDE_ 33      // padded reduction row stride (conflict-free)

// Scratch
__device__ float g_feat[B_ * FEAT_];
__device__ float g_scale[FEAT_];
__device__ float g_shift[FEAT_];

#define K1_WARPS_   8                              // 4 batches x 2 window-halves
#define K1_THREADS_ (K1_WARPS_ * 32)
#define RED_FLOATS_ (K1_WARPS_ * 32 * RSTRIDE_)
#define K1_DSMEM_   (RED_FLOATS_ * sizeof(float))

// ---------------------------------------------------------------------------
// Per-warp accumulation over NW windows starting at window NB0.
// Batched float4 x-loads (MLP=NW), shapelet float4 streamed from smem.
// Ends with smem transpose reduction; totals land in base[0 .. NW*(NS+1)).
// Layout: [0..NW) = sx2 per window, [NW + s*NW + j] = cross(s, window j).
// ---------------------------------------------------------------------------
template<int NW, int NB0>
__device__ __forceinline__ void acc_half(const float* __restrict__ xr,
                                         const float (*s_shp)[BAGP_],
                                         const int lane,
                                         float* base)
{
    float c[NS_][NW];
    float sx2[NW];
#pragma unroll
    for (int s = 0; s < NS_; s++)
#pragma unroll
        for (int j = 0; j < NW; j++) c[s][j] = 0.f;
#pragma unroll
    for (int j = 0; j < NW; j++) sx2[j] = 0.f;

    const float* __restrict__ xr4 = xr + 4 * lane;

#pragma unroll
    for (int k = 0; k < 3; k++) {
        float4 xv[NW];
#pragma unroll
        for (int j = 0; j < NW; j++)
            xv[j] = *(const float4*)(xr4 + (NB0 + j) * SHIFT_ + 128 * k);

#pragma unroll
        for (int j = 0; j < NW; j++) {
            sx2[j] = fmaf(xv[j].x, xv[j].x, sx2[j]);
            sx2[j] = fmaf(xv[j].y, xv[j].y, sx2[j]);
            sx2[j] = fmaf(xv[j].z, xv[j].z, sx2[j]);
            sx2[j] = fmaf(xv[j].w, xv[j].w, sx2[j]);
        }
#pragma unroll
        for (int s = 0; s < NS_; s++) {
            const float4 sw = *(const float4*)(&s_shp[s][128 * k + 4 * lane]);
#pragma unroll
            for (int j = 0; j < NW; j++) {
                c[s][j] = fmaf(xv[j].x, sw.x, c[s][j]);
                c[s][j] = fmaf(xv[j].y, sw.y, c[s][j]);
                c[s][j] = fmaf(xv[j].z, sw.z, c[s][j]);
                c[s][j] = fmaf(xv[j].w, sw.w, c[s][j]);
            }
        }
    }

    // scalar tail: t = 384 + lane, valid for lane < 25
    {
        const int t = 384 + lane;
        const bool ok = (lane < 25);
        float xs[NW];
#pragma unroll
        for (int j = 0; j < NW; j++)
            xs[j] = ok ? xr[(NB0 + j) * SHIFT_ + t] : 0.f;
#pragma unroll
        for (int j = 0; j < NW; j++)
            sx2[j] = fmaf(xs[j], xs[j], sx2[j]);
#pragma unroll
        for (int s = 0; s < NS_; s++) {
            const float sv = s_shp[s][t];    // zero-padded, xs masked
#pragma unroll
            for (int j = 0; j < NW; j++)
                c[s][j] = fmaf(xs[j], sv, c[s][j]);
        }
    }

    // ---- smem transpose reduction (per warp) ----
    float* my = base + lane * RSTRIDE_;
#pragma unroll
    for (int j = 0; j < NW; j++) my[j] = sx2[j];
#pragma unroll
    for (int s = 0; s < NS_; s++)
#pragma unroll
        for (int j = 0; j < NW; j++) my[NW + s * NW + j] = c[s][j];
    __syncwarp();

    constexpr int NACC = NW * (NS_ + 1);     // 30 or 24
    float tot = 0.f;
    if (lane < NACC) {
        float a0 = 0.f, a1 = 0.f;
#pragma unroll
        for (int l = 0; l < 32; l += 2) {
            a0 += base[l * RSTRIDE_ + lane];
            a1 += base[(l + 1) * RSTRIDE_ + lane];
        }
        tot = a0 + a1;
    }
    __syncwarp();
    if (lane < NACC) base[lane] = tot;
}

// ---------------------------------------------------------------------------
// Kernel 1: block = (4 batches, 1 v), warp pair per (b,v): half0 -> windows
// 0..4, half1 -> windows 5..8. Grid 512, 4096 warps (2x R7), single wave.
// ---------------------------------------------------------------------------
__global__ __launch_bounds__(K1_THREADS_, 4)
void shapelet_feat_kernel(const float* __restrict__ x,
                          const float* __restrict__ shp,
                          float* __restrict__ feat)
{
    extern __shared__ float red[];          // [8][32][RSTRIDE_]
    __shared__ float s_shp[NS_][BAGP_];
    __shared__ float s_ss2[NS_];

    const int tid  = threadIdx.x;
    const int warp = tid >> 5;
    const int lane = tid & 31;
    const int half = warp & 1;
    const int v  = blockIdx.x & 7;
    const int b  = (blockIdx.x >> 3) * 4 + (warp >> 1);

    // Stage shapelets (zero-pad 409..415)
    for (int i = tid; i < NS_ * BAGP_; i += K1_THREADS_) {
        const int s = i / BAGP_;
        const int t = i - s * BAGP_;
        s_shp[s][t] = (t < BAG_) ? shp[s * (V_ * BAG_) + v * BAG_ + t] : 0.f;
    }
    __syncthreads();

    // ss2[s]: warps 0..4, one shapelet each
    if (warp < NS_) {
        float q = 0.f;
        for (int t = lane; t < BAG_; t += 32) {
            const float sv = s_shp[warp][t];
            q = fmaf(sv, sv, q);
        }
#pragma unroll
        for (int o = 16; o > 0; o >>= 1) q += __shfl_xor_sync(0xffffffffu, q, o);
        if (lane == 0) s_ss2[warp] = q;
    }

    const float* __restrict__ xr = x + (size_t)b * (V_ * L_) + (size_t)v * L_;
    float* base = red + warp * (32 * RSTRIDE_);

    if (half == 0) acc_half<5, 0>(xr, s_shp, lane, base);
    else           acc_half<4, 5>(xr, s_shp, lane, base);

    __syncthreads();                         // totals + s_ss2 visible

    // Epilogue: half-0 warp of each pair, lanes 0..4 = shapelet s
    if (half == 0 && lane < NS_) {
        const int s = lane;
        const float* baseA = base;                       // windows 0..4
        const float* baseB = base + 32 * RSTRIDE_;       // partner: windows 5..8
        const float ss2v = s_ss2[s];
        float dmin = 3.402823466e+38f;
        float dsum = 0.f;
#pragma unroll
        for (int j = 0; j < 5; j++) {
            const float d2 = baseA[j] + ss2v - 2.f * baseA[5 + s * 5 + j];
            const float d  = sqrtf(fmaxf(d2, 0.f));
            dmin = fminf(dmin, d);
            dsum += d;
        }
#pragma unroll
        for (int j = 0; j < 4; j++) {
            const float d2 = baseB[j] + ss2v - 2.f * baseB[4 + s * 4 + j];
            const float d  = sqrtf(fmaxf(d2, 0.f));
            dmin = fminf(dmin, d);
            dsum += d;
        }
        float* fout = feat + (size_t)b * FEAT_;
        fout[s * V_ + v]            = dmin;
        fout[NS_ * V_ + s * V_ + v] = dsum * (1.f / 9.f);
    }
}

// ---------------------------------------------------------------------------
// Kernel 2a: BN batch stats (two-pass). One block per feature, one thread per
// batch row. Writes scale[f] = gamma*rstd, shift[f] = beta - mu*scale.
// ---------------------------------------------------------------------------
__global__ __launch_bounds__(256, 8)
void bn_stats_kernel(const float* __restrict__ feat,
                     const float* __restrict__ gamma,
                     const float* __restrict__ beta,
                     float* __restrict__ scale,
                     float* __restrict__ shift)
{
    const int f = blockIdx.x;
    const int tid = threadIdx.x;
    __shared__ float ws[8];
    __shared__ float wq[8];

    const float v = feat[tid * FEAT_ + f];

    float s = v;
#pragma unroll
    for (int o = 16; o > 0; o >>= 1) s += __shfl_xor_sync(0xffffffffu, s, o);
    if ((tid & 31) == 0) ws[tid >> 5] = s;
    __syncthreads();

    const float mu = (ws[0] + ws[1] + ws[2] + ws[3] +
                      ws[4] + ws[5] + ws[6] + ws[7]) * (1.f / 256.f);

    const float d = v - mu;
    float q = d * d;
#pragma unroll
    for (int o = 16; o > 0; o >>= 1) q += __shfl_xor_sync(0xffffffffu, q, o);
    if ((tid & 31) == 0) wq[tid >> 5] = q;
    __syncthreads();

    if (tid == 0) {
        const float var = (wq[0] + wq[1] + wq[2] + wq[3] +
                           wq[4] + wq[5] + wq[6] + wq[7]) * (1.f / 256.f);
        const float rstd = rsqrtf(var + BN_EPS_);
        const float sc = gamma[f] * rstd;
        scale[f] = sc;
        shift[f] = beta[f] - mu * sc;
    }
}

// ---------------------------------------------------------------------------
// Kernel 2b: FC with BN folded. One block per class, one thread per batch row.
// ---------------------------------------------------------------------------
__global__ __launch_bounds__(256, 8)
void fc_kernel(const float* __restrict__ feat,
               const float* __restrict__ scale,
               const float* __restrict__ shift,
               const float* __restrict__ w,
               const float* __restrict__ fb,
               float* __restrict__ out)
{
    const int c = blockIdx.x;
    const int b = threadIdx.x;
    __shared__ float wp[FEAT_];
    __shared__ float cbias;

    if (b < FEAT_)
        wp[b] = w[c * FEAT_ + b] * scale[b];

    if (b >= 128 && b < 160) {
        // warp 4 computes the folded bias: fb[c] + sum_f shift[f]*w[c,f]
        const int lane = b - 128;
        float a = 0.f;
        for (int f = lane; f < FEAT_; f += 32)
            a = fmaf(shift[f], w[c * FEAT_ + f], a);
#pragma unroll
        for (int o = 16; o > 0; o >>= 1) a += __shfl_xor_sync(0xffffffffu, a, o);
        if (lane == 0) cbias = a + fb[c];
    }
    __syncthreads();

    const float4* __restrict__ fr = (const float4*)(feat + b * FEAT_);
    float acc = cbias;
#pragma unroll
    for (int i = 0; i < FEAT_ / 4; i++) {
        float4 xv = fr[i];
        acc = fmaf(xv.x, wp[4 * i + 0], acc);
        acc = fmaf(xv.y, wp[4 * i + 1], acc);
        acc = fmaf(xv.z, wp[4 * i + 2], acc);
        acc = fmaf(xv.w, wp[4 * i + 3], acc);
    }
    out[b * NCLASS_ + c] = acc;
}

// ---------------------------------------------------------------------------
extern "C" void kernel_launch(void* const* d_in, const int* in_sizes, int n_in,
                              void* d_out, int out_size)
{
    const float* x     = (const float*)d_in[0];  // [256, 2048, 8]
    const float* shp   = (const float*)d_in[1];  // [1, 5, 8, 409, 1]
    const float* gamma = (const float*)d_in[2];  // [80]
    const float* beta  = (const float*)d_in[3];  // [80]
    const float* fcw   = (const float*)d_in[4];  // [10, 80]
    const float* fcb   = (const float*)d_in[5];  // [10]
    float* out = (float*)d_out;                  // [256, 10]

    float *feat = nullptr, *scale = nullptr, *shift = nullptr;
    cudaGetSymbolAddress((void**)&feat,  g_feat);
    cudaGetSymbolAddress((void**)&scale, g_scale);
    cudaGetSymbolAddress((void**)&shift, g_shift);

    shapelet_feat_kernel<<<512, K1_THREADS_, K1_DSMEM_>>>(x, shp, feat);
    bn_stats_kernel<<<FEAT_, 256>>>(feat, gamma, beta, scale, shift);
    fc_kernel<<<NCLASS_, 256>>>(feat, scale, shift, fcw, fcb, out);
}